// round 8
// baseline (speedup 1.0000x reference)
#include <cuda_runtime.h>

#define N_ROWS 100000
#define IC 256
#define OC 64
#define NH 8
#define HC 512
#define C3 1536
#define KTV_SZ (NH*OC*OC)

__device__ float g_W[IC * C3];
__device__ float g_b[C3];
__device__ float g_Z[(size_t)N_ROWS * C3];
__device__ float g_kTv[KTV_SZ];
__device__ float g_sumk[HC];

typedef unsigned long long u64;

__device__ __forceinline__ u64 pk2(float x, float y) {
    u64 r; asm("mov.b64 %0, {%1,%2};" : "=l"(r) : "f"(x), "f"(y)); return r;
}
__device__ __forceinline__ void fma2(u64& d, u64 a, u64 b) {
    asm("fma.rn.f32x2 %0, %1, %2, %0;" : "+l"(d) : "l"(a), "l"(b));
}
__device__ __forceinline__ float2 up2(u64 v) {
    float lo, hi; asm("mov.b64 {%0,%1}, %2;" : "=f"(lo), "=f"(hi) : "l"(v));
    return make_float2(lo, hi);
}

// ---------------- prep: pack weights, zero accumulators --------------------
__global__ void k_prep(const float* __restrict__ Wq, const float* __restrict__ bq,
                       const float* __restrict__ Wk, const float* __restrict__ bk,
                       const float* __restrict__ Wv, const float* __restrict__ bv) {
    int i = blockIdx.x * blockDim.x + threadIdx.x;
    if (i < IC * C3) {
        int k = i / C3, c = i - k * C3;
        int part = c >> 9, cc = c & 511;
        int h = cc >> 6, o = cc & 63;
        const float* W = (part == 0) ? Wq : (part == 1) ? Wk : Wv;
        g_W[i] = W[(h * IC + k) * OC + o];
    }
    if (i < C3) {
        int part = i >> 9, cc = i & 511;
        const float* B = (part == 0) ? bq : (part == 1) ? bk : bv;
        g_b[i] = B[cc];
    }
    if (i < KTV_SZ) g_kTv[i] = 0.f;
    if (i < HC)     g_sumk[i] = 0.f;
}

// ---------------- SGEMM: Z = X @ g_W + g_b ---------------------------------
#define BM 128
#define BN 128
#define BK 8

__global__ void __launch_bounds__(256, 2) k_gemm(const float* __restrict__ X) {
    __shared__ __align__(16) float As[BK][BM];
    __shared__ __align__(16) float Bs[BK][BN];
    int tid = threadIdx.x;
    int tx = tid & 15, ty = tid >> 4;
    int row0 = blockIdx.y * BM, col0 = blockIdx.x * BN;
    int xr = tid >> 1, xk = (tid & 1) * 4;
    int wk = tid >> 5, wc = (tid & 31) * 4;

    u64 acc[8][4];
#pragma unroll
    for (int i = 0; i < 8; i++)
        acc[i][0] = acc[i][1] = acc[i][2] = acc[i][3] = 0ull;

    float4 xv, wv;
    {
        int r = row0 + xr;
        xv = (r < N_ROWS) ? *(const float4*)&X[r * IC + xk]
                          : make_float4(0.f, 0.f, 0.f, 0.f);
        wv = *(const float4*)&g_W[wk * C3 + col0 + wc];
    }

    for (int kt = 0; kt < IC; kt += BK) {
        As[xk + 0][xr] = xv.x; As[xk + 1][xr] = xv.y;
        As[xk + 2][xr] = xv.z; As[xk + 3][xr] = xv.w;
        *(float4*)&Bs[wk][wc] = wv;
        __syncthreads();

        int kn = kt + BK;
        if (kn < IC) {
            int r = row0 + xr;
            xv = (r < N_ROWS) ? *(const float4*)&X[r * IC + kn + xk]
                              : make_float4(0.f, 0.f, 0.f, 0.f);
            wv = *(const float4*)&g_W[(kn + wk) * C3 + col0 + wc];
        }

#pragma unroll
        for (int kk = 0; kk < BK; kk++) {
            float4 a0 = *(const float4*)&As[kk][ty * 8];
            float4 a1 = *(const float4*)&As[kk][ty * 8 + 4];
            ulonglong2 b0 = *(const ulonglong2*)&Bs[kk][tx * 8];
            ulonglong2 b1 = *(const ulonglong2*)&Bs[kk][tx * 8 + 4];
            u64 av[8];
            av[0] = pk2(a0.x, a0.x); av[1] = pk2(a0.y, a0.y);
            av[2] = pk2(a0.z, a0.z); av[3] = pk2(a0.w, a0.w);
            av[4] = pk2(a1.x, a1.x); av[5] = pk2(a1.y, a1.y);
            av[6] = pk2(a1.z, a1.z); av[7] = pk2(a1.w, a1.w);
#pragma unroll
            for (int i = 0; i < 8; i++) {
                fma2(acc[i][0], av[i], b0.x);
                fma2(acc[i][1], av[i], b0.y);
                fma2(acc[i][2], av[i], b1.x);
                fma2(acc[i][3], av[i], b1.y);
            }
        }
        __syncthreads();
    }

    int cbase = col0 + tx * 8;
    float4 bias0 = *(const float4*)&g_b[cbase];
    float4 bias1 = *(const float4*)&g_b[cbase + 4];
#pragma unroll
    for (int i = 0; i < 8; i++) {
        int row = row0 + ty * 8 + i;
        if (row >= N_ROWS) break;
        float2 c0 = up2(acc[i][0]), c1 = up2(acc[i][1]);
        float2 c2 = up2(acc[i][2]), c3 = up2(acc[i][3]);
        float4 o0 = make_float4(c0.x + bias0.x, c0.y + bias0.y,
                                c1.x + bias0.z, c1.y + bias0.w);
        float4 o1 = make_float4(c2.x + bias1.x, c2.y + bias1.y,
                                c3.x + bias1.z, c3.y + bias1.w);
        *(float4*)&g_Z[(size_t)row * C3 + cbase] = o0;
        *(float4*)&g_Z[(size_t)row * C3 + cbase + 4] = o1;
    }
}

// ---------------- phi_k in place over k-region of Z ------------------------
__global__ void k_phik(const float* __restrict__ nscale) {
    int idx = blockIdx.x * blockDim.x + threadIdx.x;   // 0..799999
    int n = idx >> 3, h = idx & 7;
    float inv = 1.0f / (fabsf(*nscale) + 1e-6f);
    float* z = &g_Z[(size_t)n * C3 + HC + h * OC];
    float sq[64];
    float na = 0.f, nb = 0.f;
#pragma unroll
    for (int i = 0; i < 16; i++) {
        float4 v = *(const float4*)&z[i * 4];
        float s0 = (fmaxf(v.x, 0.f) + 1e-6f) * inv;
        float s1 = (fmaxf(v.y, 0.f) + 1e-6f) * inv;
        float s2 = (fmaxf(v.z, 0.f) + 1e-6f) * inv;
        float s3 = (fmaxf(v.w, 0.f) + 1e-6f) * inv;
        float q0 = s0 * s0, q1 = s1 * s1, q2 = s2 * s2, q3 = s3 * s3;
        sq[i * 4 + 0] = q0; sq[i * 4 + 1] = q1;
        sq[i * 4 + 2] = q2; sq[i * 4 + 3] = q3;
        na += q0 + q1 + q2 + q3;
        nb += q0 * q0 + q1 * q1 + q2 * q2 + q3 * q3;
    }
    float scale = sqrtf(na) / (sqrtf(nb) + 1e-12f);
#pragma unroll
    for (int i = 0; i < 16; i++) {
        float4 o = make_float4(sq[i*4] * scale, sq[i*4+1] * scale,
                               sq[i*4+2] * scale, sq[i*4+3] * scale);
        *(float4*)&z[i * 4] = o;
    }
}

// ---------------- kTv / sumk reduction --------------------------------------
#define RBLK 148

__global__ void __launch_bounds__(512, 1) k_ktv() {
    int tid = threadIdx.x;
    int h = tid >> 6, t6 = tid & 63;
    int m0 = (t6 >> 3) * 8, d0 = (t6 & 7) * 8;

    u64 acc[8][4];
#pragma unroll
    for (int i = 0; i < 8; i++)
        acc[i][0] = acc[i][1] = acc[i][2] = acc[i][3] = 0ull;
    float sk[8] = {0,0,0,0,0,0,0,0};

    int per = (N_ROWS + RBLK - 1) / RBLK;
    int rbeg = blockIdx.x * per;
    int rend = min(rbeg + per, N_ROWS);

    for (int r = rbeg; r < rend; r++) {
        const float* base = &g_Z[(size_t)r * C3];
        float4 p0 = __ldg((const float4*)&base[HC + h * OC + m0]);
        float4 p1 = __ldg((const float4*)&base[HC + h * OC + m0 + 4]);
        float4 v0 = __ldg((const float4*)&base[2 * HC + h * OC + d0]);
        float4 v1 = __ldg((const float4*)&base[2 * HC + h * OC + d0 + 4]);
        u64 vv[4] = { pk2(v0.x, v0.y), pk2(v0.z, v0.w),
                      pk2(v1.x, v1.y), pk2(v1.z, v1.w) };
        float p[8] = { p0.x, p0.y, p0.z, p0.w, p1.x, p1.y, p1.z, p1.w };
#pragma unroll
        for (int i = 0; i < 8; i++) {
            u64 pp = pk2(p[i], p[i]);
            fma2(acc[i][0], pp, vv[0]);
            fma2(acc[i][1], pp, vv[1]);
            fma2(acc[i][2], pp, vv[2]);
            fma2(acc[i][3], pp, vv[3]);
            if (d0 == 0) sk[i] += p[i];
        }
    }
#pragma unroll
    for (int i = 0; i < 8; i++) {
#pragma unroll
        for (int j = 0; j < 4; j++) {
            float2 c = up2(acc[i][j]);
            int m = m0 + i, dd = d0 + j * 2;
            atomicAdd(&g_kTv[(h * OC + m) * OC + dd],     c.x);
            atomicAdd(&g_kTv[(h * OC + m) * OC + dd + 1], c.y);
        }
    }
    if (d0 == 0)
#pragma unroll
        for (int i = 0; i < 8; i++)
            atomicAdd(&g_sumk[h * OC + m0 + i], sk[i]);
}

// ---------------- fused output ----------------------------------------------
#define HPAD 4100                      // 4096 + 4 (bank de-conflict per head)
#define SM_KV (NH * HPAD)              // 32800
#define SM_TOT (SM_KV + 4096 + 512 + 64 + 2048 + 2048)

__global__ void __launch_bounds__(256, 1) k_out(const float* __restrict__ nscale,
                                                const float* __restrict__ Wm,
                                                const float* __restrict__ bm,
                                                float* __restrict__ out) {
    extern __shared__ __align__(16) float sm[];
    float* s_kv   = sm;                 // head h at h*HPAD
    float* s_wm   = s_kv + SM_KV;       // 4096
    float* s_sumk = s_wm + 4096;        // 512
    float* s_bm   = s_sumk + 512;       // 64
    float* s_vbar = s_bm + 64;          // 32*64
    float* s_out  = s_vbar + 2048;      // 32*64

    int tid = threadIdx.x;
    int row0 = blockIdx.x * 32;
    float inv = 1.0f / (fabsf(*nscale) + 1e-6f);

    for (int i = tid; i < KTV_SZ; i += 256)
        s_kv[(i >> 12) * HPAD + (i & 4095)] = g_kTv[i];
    for (int i = tid; i < 4096; i += 256) s_wm[i] = Wm[i];
    if (tid < 256) { s_sumk[tid] = g_sumk[tid]; s_sumk[tid + 256] = g_sumk[tid + 256]; }
    if (tid < 64) s_bm[tid] = bm[tid];

#pragma unroll
    for (int j = 0; j < 8; j++) {                 // vbar = mean_h v
        int idx = tid + j * 256;
        int r = idx >> 6, e = idx & 63;
        const float* vz = &g_Z[(size_t)(row0 + r) * C3 + 2 * HC + e];
        float s = 0.f;
#pragma unroll
        for (int h = 0; h < NH; h++) s += vz[h * OC];
        s_vbar[idx] = s * 0.125f;
    }
    __syncthreads();

    int r = tid >> 3, h = tid & 7;

    // phi_q for this (row, head)
    float sq[64];
    {
        const float* zq = &g_Z[(size_t)(row0 + r) * C3 + h * OC];
        float na = 0.f, nb = 0.f;
#pragma unroll
        for (int i = 0; i < 16; i++) {
            float4 z = *(const float4*)&zq[i * 4];
            float s0 = (fmaxf(z.x, 0.f) + 1e-6f) * inv;
            float s1 = (fmaxf(z.y, 0.f) + 1e-6f) * inv;
            float s2 = (fmaxf(z.z, 0.f) + 1e-6f) * inv;
            float s3 = (fmaxf(z.w, 0.f) + 1e-6f) * inv;
            float q0 = s0*s0, q1 = s1*s1, q2 = s2*s2, q3 = s3*s3;
            sq[i*4] = q0; sq[i*4+1] = q1; sq[i*4+2] = q2; sq[i*4+3] = q3;
            na += q0 + q1 + q2 + q3;
            nb += q0*q0 + q1*q1 + q2*q2 + q3*q3;
        }
        float scale = sqrtf(na) / (sqrtf(nb) + 1e-12f);
        float den = 0.f;
#pragma unroll
        for (int m = 0; m < 64; m++) {
            sq[m] *= scale;
            den += sq[m] * s_sumk[h * OC + m];
        }
        den += 1e-6f;
        float w = 0.125f / den;                   // fold head-mean 1/8
#pragma unroll
        for (int m = 0; m < 64; m++) sq[m] *= w;  // phi_q * w
    }

    const float* kvh = &s_kv[h * HPAD];
#pragma unroll 1
    for (int ep = 0; ep < 32; ep++) {
        u64 a2 = 0ull;
        int e = ep * 2;
#pragma unroll
        for (int m = 0; m < 64; m++)
            fma2(a2, pk2(sq[m], sq[m]), *(const u64*)&kvh[m * OC + e]);
        float2 f = up2(a2);
        float v0 = f.x, v1 = f.y;
#pragma unroll
        for (int off = 1; off < 8; off <<= 1) {   // sum over 8 head lanes
            v0 += __shfl_xor_sync(0xffffffffu, v0, off);
            v1 += __shfl_xor_sync(0xffffffffu, v1, off);
        }
        if (h == 0) { s_out[r * 64 + e] = v0; s_out[r * 64 + e + 1] = v1; }
    }
    __syncthreads();

    // residual: vbar @ Wm + bm ; thread handles e in [h*8, h*8+8)
    {
        const float* vb = &s_vbar[r * 64];
#pragma unroll
        for (int j = 0; j < 4; j++) {
            int e0 = h * 8 + j * 2;
            u64 a2 = 0ull;
#pragma unroll
            for (int d = 0; d < 64; d++)
                fma2(a2, pk2(vb[d], vb[d]), *(const u64*)&s_wm[d * OC + e0]);
            float2 f = up2(a2);
            s_out[r * 64 + e0]     += f.x + s_bm[e0];
            s_out[r * 64 + e0 + 1] += f.y + s_bm[e0 + 1];
        }
    }
    __syncthreads();

    // Lorentz lift and store
    {
        float part = 0.f;
        float vals[8];
#pragma unroll
        for (int j = 0; j < 8; j++) {
            vals[j] = s_out[r * 64 + h * 8 + j];
            part += vals[j] * vals[j];
        }
#pragma unroll
        for (int off = 1; off < 8; off <<= 1)
            part += __shfl_xor_sync(0xffffffffu, part, off);
        float* orow = &out[(size_t)(row0 + r) * 65];
        if (h == 0) orow[0] = sqrtf(part + 1.0f);
#pragma unroll
        for (int j = 0; j < 8; j++) orow[1 + h * 8 + j] = vals[j];
    }
}

// ---------------- launch ----------------------------------------------------
extern "C" void kernel_launch(void* const* d_in, const int* in_sizes, int n_in,
                              void* d_out, int out_size) {
    const float* X      = (const float*)d_in[0];
    const float* Wq     = (const float*)d_in[1];
    const float* bq     = (const float*)d_in[2];
    const float* Wk     = (const float*)d_in[3];
    const float* bk     = (const float*)d_in[4];
    const float* Wv     = (const float*)d_in[5];
    const float* bv     = (const float*)d_in[6];
    const float* nscale = (const float*)d_in[7];
    const float* Wm     = (const float*)d_in[8];
    const float* bm     = (const float*)d_in[9];
    float* out = (float*)d_out;

    static bool attr_set = false;
    if (!attr_set) {
        cudaFuncSetAttribute(k_out, cudaFuncAttributeMaxDynamicSharedMemorySize,
                             SM_TOT * (int)sizeof(float));
        attr_set = true;
    }

    k_prep<<<512, 768>>>(Wq, bq, Wk, bk, Wv, bv);
    k_gemm<<<dim3(12, (N_ROWS + BM - 1) / BM), 256>>>(X);
    k_phik<<<3125, 256>>>(nscale);
    k_ktv<<<RBLK, 512>>>();
    k_out<<<3125, 256, SM_TOT * sizeof(float)>>>(nscale, Wm, bm, out);
}